// round 12
// baseline (speedup 1.0000x reference)
#include <cuda_runtime.h>
#include <cstdint>

#define T_STEPS 2048
#define BATCH   64
#define IN_DIM  128
#define HDIM    256
#define OUT_DIM 128
#define NTHR    512
#define NBLK    128           // 32 groups (2 rows) x 8 ranks; 2 groups per CTA
#define WOPAD   272

// smem layout (floats)
#define OFF_ACT   0                       // [2 chain][2 buf][384*2] = 3072
#define OFF_WOUT  3072                    // [16][272] = 4352
#define OFF_P     7424                    // [4][128][2] = 1024
#define OFF_G     8448                    // [128][2] = 256
#define OFF_BIAS  8704                    // 128
#define OFF_BOUT  8832                    // 16
#define SMEM_FLOATS 8848
#define SMEM_BYTES (SMEM_FLOATS * 4)      // 35392

// persistent state: transposed h per group, double-buffered
__device__ float g_hT[32][2][HDIM * 2];   // [grp][buf][col*2 + r]
struct Flag { unsigned v; unsigned pad[31]; };
__device__ Flag g_flags[256];             // [grp*8 + rank]

__device__ __forceinline__ unsigned ld_acq(const unsigned* p) {
    unsigned v;
    asm volatile("ld.acquire.gpu.global.u32 %0, [%1];" : "=r"(v) : "l"(p) : "memory");
    return v;
}
__device__ __forceinline__ void st_rel(unsigned* p, unsigned v) {
    asm volatile("st.release.gpu.global.u32 [%0], %1;" :: "l"(p), "r"(v) : "memory");
}
__device__ __forceinline__ float sigm(float x) { return 1.0f / (1.0f + __expf(-x)); }
__device__ __forceinline__ float tanh_fast(float x) {
    return 2.0f / (1.0f + __expf(-2.0f * x)) - 1.0f;
}

// f32x2 GEMM over N k-pairs; weights from wreg[wbase..], activation pairs at
// (ull*)Abase + koff. kq is warp-uniform -> LDS.64 broadcasts, conflict-free.
#define GEMM_LOOP(Abase, koff, wbase, N, ACC) do {                              \
    const unsigned long long* _av = ((const unsigned long long*)(Abase)) + (koff); \
    _Pragma("unroll")                                                            \
    for (int _i = 0; _i < (N); _i++) {                                           \
        unsigned long long _p = _av[_i];                                         \
        unsigned _wu = __float_as_uint(wreg[(wbase) + _i]);                      \
        unsigned long long _wp;                                                  \
        asm("mov.b64 %0, {%1, %1};" : "=l"(_wp) : "r"(_wu));                     \
        asm("fma.rn.f32x2 %0, %1, %2, %0;" : "+l"(ACC) : "l"(_wp), "l"(_p));     \
    }                                                                            \
} while (0)

__global__ void __launch_bounds__(NTHR, 1) lstm_dual_kernel(
    const float* __restrict__ input,   // [T, B, IN]
    const float* __restrict__ W_ih,    // [4H, IN]
    const float* __restrict__ W_hh,    // [4H, H]
    const float* __restrict__ b_ih,    // [4H]
    const float* __restrict__ b_hh,    // [4H]
    const float* __restrict__ W_out,   // [OUT, H]
    const float* __restrict__ b_out,   // [OUT]
    float* __restrict__ out,
    int out_size)
{
    extern __shared__ float sm[];
    float* sWo   = sm + OFF_WOUT;
    float* sBias = sm + OFF_BIAS;
    float* sBOut = sm + OFF_BOUT;

    const int tid  = threadIdx.x;
    const int bid  = blockIdx.x;
    const int rank = bid & 7;
    const int gA   = (bid >> 3) * 2;       // chain A group
    const int gB   = gA + 1;               // chain B group
    const int cb   = rank * 32;

    const unsigned base = ld_acq(&g_flags[gA * 8 + rank].v);   // uniform

    // ---- GEMM mapping: m = tid&127 (gate-col), kq = tid>>7 (warp-uniform) ----
    const int m   = tid & 127;
    const int kq  = tid >> 7;
    const int g_  = m >> 5;
    const int col = m & 31;
    const int grow = g_ * HDIM + cb + col;

    // ---- weights in registers (shared by both chains) ----
    float wreg[96];
    {
        const float* src_ih = W_ih + (size_t)grow * IN_DIM + kq * 32;
        const float* src_hh = W_hh + (size_t)grow * HDIM + kq * 64;
        #pragma unroll
        for (int i = 0; i < 32; i++) wreg[i] = __ldg(src_ih + i);
        #pragma unroll
        for (int i = 0; i < 64; i++) wreg[32 + i] = __ldg(src_hh + i);
    }

    // ---- smem preload ----
    for (int i = tid; i < 16 * HDIM; i += NTHR) {
        int o = i >> 8, k = i & 255;
        sWo[o * WOPAD + k] = W_out[(rank * 16 + o) * HDIM + k];
    }
    if (tid < 128) sBias[tid] = b_ih[grow] + b_hh[grow];
    if (tid < 16) sBOut[tid] = b_out[rank * 16 + tid];

    // zero act buffers (h_0 = 0), x_0 for both chains into buf0
    for (int i = tid; i < 3072; i += NTHR) sm[OFF_ACT + i] = 0.0f;
    __syncthreads();
    if (tid < 128) {
        int ch = tid >> 6, rr = (tid >> 5) & 1, k5 = tid & 31;
        int row = (gA + ch) * 2 + rr;
        float4 v = *(const float4*)(input + (size_t)row * IN_DIM + k5 * 4);
        float* dst = sm + OFF_ACT + ch * 1536;   // buf0
        dst[(k5 * 4 + 0) * 2 + rr] = v.x;
        dst[(k5 * 4 + 1) * 2 + rr] = v.y;
        dst[(k5 * 4 + 2) * 2 + rr] = v.z;
        dst[(k5 * 4 + 3) * 2 + rr] = v.w;
    }
    __syncthreads();

    const size_t Y_TOTAL = (size_t)T_STEPS * BATCH * OUT_DIM;
    const bool write_tail = (out_size >= (int)(Y_TOTAL + 2 * BATCH * HDIM));

    float csA0 = 0.f, csA1 = 0.f, csB0 = 0.f, csB1 = 0.f;   // cell states (tid<32)

    for (int t = 0; t < T_STEPS; t++) {
        const int buf  = t & 1;
        const int bufn = buf ^ 1;
        float* AA = sm + OFF_ACT + buf * 768;
        float* AB = sm + OFF_ACT + 1536 + buf * 768;
        const unsigned need = base + (unsigned)t;
        const unsigned tgt  = need + 1;

        // ================= chain A =================
        if (t > 0) {
            if (tid < 8) {
                const unsigned* p = &g_flags[gA * 8 + tid].v;
                while (ld_acq(p) < need) { }
            }
            __syncthreads();
        }
        float4 hvA;
        if (t > 0 && tid < 128)
            hvA = __ldcg(((const float4*)g_hT[gA][buf]) + tid);

        // x-part GEMMs for BOTH chains (covers hvA latency)
        unsigned long long accA = 0ULL, accB = 0ULL;
        GEMM_LOOP(AA, kq * 32, 0, 32, accA);
        GEMM_LOOP(AB, kq * 32, 0, 32, accB);

        if (t > 0 && tid < 128)
            ((float4*)(AA + 256))[tid] = hvA;
        __syncthreads();

        // h-part GEMM chain A
        GEMM_LOOP(AA, 128 + kq * 64, 32, 64, accA);
        {
            unsigned u0, u1;
            asm("mov.b64 {%0,%1}, %2;" : "=r"(u0), "=r"(u1) : "l"(accA));
            ((float2*)(sm + OFF_P))[kq * 128 + m] =
                make_float2(__uint_as_float(u0), __uint_as_float(u1));
        }
        __syncthreads();

        if (tid < 128) {
            const float2* p2 = (const float2*)(sm + OFF_P);
            float2 a = p2[tid], b2 = p2[128 + tid], c2 = p2[256 + tid], d2 = p2[384 + tid];
            float bb = sBias[tid];
            ((float2*)(sm + OFF_G))[tid] =
                make_float2(a.x + b2.x + c2.x + d2.x + bb, a.y + b2.y + c2.y + d2.y + bb);
            asm volatile("bar.sync 1, 128;" ::: "memory");
            if (tid < 32) {
                const float* sG = sm + OFF_G;
                int c = tid;
                float i0 = sigm(sG[(0  + c) * 2 + 0]), i1 = sigm(sG[(0  + c) * 2 + 1]);
                float f0 = sigm(sG[(32 + c) * 2 + 0]), f1 = sigm(sG[(32 + c) * 2 + 1]);
                float q0 = tanh_fast(sG[(64 + c) * 2 + 0]), q1 = tanh_fast(sG[(64 + c) * 2 + 1]);
                float o0 = sigm(sG[(96 + c) * 2 + 0]), o1 = sigm(sG[(96 + c) * 2 + 1]);
                float cn0 = f0 * csA0 + i0 * q0, cn1 = f1 * csA1 + i1 * q1;
                float hn0 = o0 * tanh_fast(cn0), hn1 = o1 * tanh_fast(cn1);
                csA0 = cn0; csA1 = cn1;
                __stcg((float2*)&g_hT[gA][bufn][(cb + c) * 2], make_float2(hn0, hn1));
                if (t == T_STEPS - 1 && write_tail) {
                    size_t r0 = (size_t)(gA * 2) * HDIM + cb + c;
                    out[Y_TOTAL + r0] = hn0;
                    out[Y_TOTAL + r0 + HDIM] = hn1;
                    out[Y_TOTAL + BATCH * HDIM + r0] = cn0;
                    out[Y_TOTAL + BATCH * HDIM + r0 + HDIM] = cn1;
                }
            }
            asm volatile("bar.sync 1, 128;" ::: "memory");
            if (tid == 0) st_rel(&g_flags[gA * 8 + rank].v, tgt);
        }

        // ================= chain B =================
        if (t > 0 && tid < 8) {
            const unsigned* p = &g_flags[gB * 8 + tid].v;
            while (ld_acq(p) < need) { }
        }
        __syncthreads();
        float4 hvB;
        if (t > 0 && tid < 128)
            hvB = __ldcg(((const float4*)g_hT[gB][buf]) + tid);

        // B-fill window work: y_A (warps 8-15) + x-prefetch both chains (warps 4-7)
        if (tid >= 256 && t > 0) {
            const int slot = tid - 256;
            const int o = slot >> 4, ks = slot & 15;
            float y0 = 0.f, y1 = 0.f;
            const float* wo = sWo + o * WOPAD + ks;
            const float2* ah = ((const float2*)AA) + 128 + ks;
            #pragma unroll
            for (int i = 0; i < 16; i++) {
                float w = wo[i * 16];
                float2 h2 = ah[i * 16];
                y0 += w * h2.x; y1 += w * h2.y;
            }
            #pragma unroll
            for (int s = 1; s <= 8; s <<= 1) {
                y0 += __shfl_xor_sync(0xffffffffu, y0, s);
                y1 += __shfl_xor_sync(0xffffffffu, y1, s);
            }
            if (ks == 0) {
                float b = sBOut[o];
                size_t yb = ((size_t)(t - 1) * BATCH + gA * 2) * OUT_DIM + rank * 16 + o;
                out[yb] = y0 + b;
                out[yb + OUT_DIM] = y1 + b;
            }
        } else if (tid >= 128 && tid < 256 && t + 1 < T_STEPS) {
            int idx = tid - 128;
            int ch = idx >> 6, rr = (idx >> 5) & 1, k5 = idx & 31;
            int row = (gA + ch) * 2 + rr;
            float4 v = __ldcg((const float4*)(input
                        + ((size_t)(t + 1) * BATCH + row) * IN_DIM + k5 * 4));
            float* dst = sm + OFF_ACT + ch * 1536 + bufn * 768;
            dst[(k5 * 4 + 0) * 2 + rr] = v.x;
            dst[(k5 * 4 + 1) * 2 + rr] = v.y;
            dst[(k5 * 4 + 2) * 2 + rr] = v.z;
            dst[(k5 * 4 + 3) * 2 + rr] = v.w;
        }
        if (t > 0 && tid < 128)
            ((float4*)(AB + 256))[tid] = hvB;
        __syncthreads();

        // h-part GEMM chain B
        GEMM_LOOP(AB, 128 + kq * 64, 32, 64, accB);
        {
            unsigned u0, u1;
            asm("mov.b64 {%0,%1}, %2;" : "=r"(u0), "=r"(u1) : "l"(accB));
            ((float2*)(sm + OFF_P))[kq * 128 + m] =
                make_float2(__uint_as_float(u0), __uint_as_float(u1));
        }
        __syncthreads();

        if (tid < 128) {
            const float2* p2 = (const float2*)(sm + OFF_P);
            float2 a = p2[tid], b2 = p2[128 + tid], c2 = p2[256 + tid], d2 = p2[384 + tid];
            float bb = sBias[tid];
            ((float2*)(sm + OFF_G))[tid] =
                make_float2(a.x + b2.x + c2.x + d2.x + bb, a.y + b2.y + c2.y + d2.y + bb);
            asm volatile("bar.sync 1, 128;" ::: "memory");
            if (tid < 32) {
                const float* sG = sm + OFF_G;
                int c = tid;
                float i0 = sigm(sG[(0  + c) * 2 + 0]), i1 = sigm(sG[(0  + c) * 2 + 1]);
                float f0 = sigm(sG[(32 + c) * 2 + 0]), f1 = sigm(sG[(32 + c) * 2 + 1]);
                float q0 = tanh_fast(sG[(64 + c) * 2 + 0]), q1 = tanh_fast(sG[(64 + c) * 2 + 1]);
                float o0 = sigm(sG[(96 + c) * 2 + 0]), o1 = sigm(sG[(96 + c) * 2 + 1]);
                float cn0 = f0 * csB0 + i0 * q0, cn1 = f1 * csB1 + i1 * q1;
                float hn0 = o0 * tanh_fast(cn0), hn1 = o1 * tanh_fast(cn1);
                csB0 = cn0; csB1 = cn1;
                __stcg((float2*)&g_hT[gB][bufn][(cb + c) * 2], make_float2(hn0, hn1));
                if (t == T_STEPS - 1 && write_tail) {
                    size_t r0 = (size_t)(gB * 2) * HDIM + cb + c;
                    out[Y_TOTAL + r0] = hn0;
                    out[Y_TOTAL + r0 + HDIM] = hn1;
                    out[Y_TOTAL + BATCH * HDIM + r0] = cn0;
                    out[Y_TOTAL + BATCH * HDIM + r0 + HDIM] = cn1;
                }
            }
            asm volatile("bar.sync 1, 128;" ::: "memory");
            if (tid == 0) st_rel(&g_flags[gB * 8 + rank].v, tgt);
        } else if (tid >= 256 && t > 0) {
            // y_{t-1} chain B (parallel with B reduce/cell)
            const int slot = tid - 256;
            const int o = slot >> 4, ks = slot & 15;
            float y0 = 0.f, y1 = 0.f;
            const float* wo = sWo + o * WOPAD + ks;
            const float2* ah = ((const float2*)AB) + 128 + ks;
            #pragma unroll
            for (int i = 0; i < 16; i++) {
                float w = wo[i * 16];
                float2 h2 = ah[i * 16];
                y0 += w * h2.x; y1 += w * h2.y;
            }
            #pragma unroll
            for (int s = 1; s <= 8; s <<= 1) {
                y0 += __shfl_xor_sync(0xffffffffu, y0, s);
                y1 += __shfl_xor_sync(0xffffffffu, y1, s);
            }
            if (ks == 0) {
                float b = sBOut[o];
                size_t yb = ((size_t)(t - 1) * BATCH + gB * 2) * OUT_DIM + rank * 16 + o;
                out[yb] = y0 + b;
                out[yb + OUT_DIM] = y1 + b;
            }
        }
        // no trailing sync: next iteration's A-poll __syncthreads joins everyone
    }

    // ---- tail: y_{T-1} from h_T (buf 0) for both chains ----
    {
        const unsigned needT = base + (unsigned)T_STEPS;
        if (tid < 8) {
            const unsigned* p = &g_flags[gA * 8 + tid].v;
            while (ld_acq(p) < needT) { }
        } else if (tid < 16) {
            const unsigned* p = &g_flags[gB * 8 + (tid - 8)].v;
            while (ld_acq(p) < needT) { }
        }
        __syncthreads();
        float* AA = sm + OFF_ACT;           // buf0
        float* AB = sm + OFF_ACT + 1536;
        if (tid < 128) {
            float4 v = __ldcg(((const float4*)g_hT[gA][0]) + tid);
            ((float4*)(AA + 256))[tid] = v;
        } else if (tid < 256) {
            float4 v = __ldcg(((const float4*)g_hT[gB][0]) + (tid - 128));
            ((float4*)(AB + 256))[tid - 128] = v;
        }
        __syncthreads();
        if (tid >= 256) {
            const int slot = tid - 256;
            const int o = slot >> 4, ks = slot & 15;
            #pragma unroll
            for (int ch = 0; ch < 2; ch++) {
                const float* Ach = ch ? AB : AA;
                const int gch = gA + ch;
                float y0 = 0.f, y1 = 0.f;
                const float* wo = sWo + o * WOPAD + ks;
                const float2* ah = ((const float2*)Ach) + 128 + ks;
                #pragma unroll
                for (int i = 0; i < 16; i++) {
                    float w = wo[i * 16];
                    float2 h2 = ah[i * 16];
                    y0 += w * h2.x; y1 += w * h2.y;
                }
                #pragma unroll
                for (int s = 1; s <= 8; s <<= 1) {
                    y0 += __shfl_xor_sync(0xffffffffu, y0, s);
                    y1 += __shfl_xor_sync(0xffffffffu, y1, s);
                }
                if (ks == 0) {
                    float b = sBOut[o];
                    size_t yb = ((size_t)(T_STEPS - 1) * BATCH + gch * 2) * OUT_DIM
                                + rank * 16 + o;
                    out[yb] = y0 + b;
                    out[yb + OUT_DIM] = y1 + b;
                }
            }
        }
    }
}

extern "C" void kernel_launch(void* const* d_in, const int* in_sizes, int n_in,
                              void* d_out, int out_size) {
    const float* input = (const float*)d_in[0];
    const float* W_ih  = (const float*)d_in[1];
    const float* W_hh  = (const float*)d_in[2];
    const float* b_ih  = (const float*)d_in[3];
    const float* b_hh  = (const float*)d_in[4];
    const float* W_out = (const float*)d_in[5];
    const float* b_out = (const float*)d_in[6];
    float* out = (float*)d_out;
    (void)in_sizes; (void)n_in;

    cudaFuncSetAttribute(lstm_dual_kernel,
                         cudaFuncAttributeMaxDynamicSharedMemorySize, SMEM_BYTES);
    lstm_dual_kernel<<<NBLK, NTHR, SMEM_BYTES>>>(
        input, W_ih, W_hh, b_ih, b_hh, W_out, b_out, out, out_size);
}

// round 13
// speedup vs baseline: 2.0515x; 2.0515x over previous
#include <cuda_runtime.h>
#include <cstdint>

#define T_STEPS 2048
#define BATCH   64
#define IN_DIM  128
#define HDIM    256
#define OUT_DIM 128
#define NTHR    512
#define NBLK    128           // 16 groups (4 batch rows) x 8 ranks (32 h-cols)
#define WOPAD   272

// smem layout (floats)
#define OFF_ACT   0                       // [2][384][4]  = 3072
#define OFF_WOUT  3072                    // [16][272]    = 4352
#define OFF_P     7424                    // [8][128][4]  = 4096
#define OFF_G     11520                   // [128][4]     = 512
#define OFF_BIAS  12032                   // 128
#define OFF_BOUT  12160                   // 16
#define SMEM_FLOATS 12176
#define SMEM_BYTES (SMEM_FLOATS * 4)      // 48704

// persistent state: transposed h, double-buffered per group
__device__ float g_hT[16][2][HDIM * 4];   // [grp][buf][col*4 + r]
struct Flag { unsigned v; unsigned pad[31]; };
__device__ Flag g_flags[NBLK];

__device__ __forceinline__ unsigned ld_acq(const unsigned* p) {
    unsigned v;
    asm volatile("ld.acquire.gpu.global.u32 %0, [%1];" : "=r"(v) : "l"(p) : "memory");
    return v;
}
__device__ __forceinline__ void st_rel(unsigned* p, unsigned v) {
    asm volatile("st.release.gpu.global.u32 [%0], %1;" :: "l"(p), "r"(v) : "memory");
}

__global__ void __launch_bounds__(NTHR, 1) lstm_col2_kernel(
    const float* __restrict__ input,   // [T, B, IN]
    const float* __restrict__ W_ih,    // [4H, IN]
    const float* __restrict__ W_hh,    // [4H, H]
    const float* __restrict__ b_ih,    // [4H]
    const float* __restrict__ b_hh,    // [4H]
    const float* __restrict__ W_out,   // [OUT, H]
    const float* __restrict__ b_out,   // [OUT]
    float* __restrict__ out,
    int out_size)
{
    extern __shared__ float sm[];
    float* sAct  = sm + OFF_ACT;   // [buf][k][r]: k<128 x, k>=128 h
    float* sWo   = sm + OFF_WOUT;
    float* sP    = sm + OFF_P;     // split-K partials [8][128][4]
    float* sG    = sm + OFF_G;     // reduced gates [m][r]
    float* sBias = sm + OFF_BIAS;
    float* sBOut = sm + OFF_BOUT;

    const int tid  = threadIdx.x;
    const int bid  = blockIdx.x;
    const int grp  = bid >> 3;
    const int rank = bid & 7;
    const int rbase = grp * 4;
    const int cb    = rank * 32;

    const unsigned base = ld_acq(&g_flags[bid].v);   // flags uniform at start

    // ---- GEMM mapping: col-pair m2 = tid&63 -> cols {2m2, 2m2+1};
    //      kq = tid>>6 (0..7) is warp-uniform -> activation LDS broadcasts ----
    const int m2 = tid & 63;
    const int kq = tid >> 6;
    const int c0 = 2 * m2, c1 = c0 + 1;
    const int grow0 = (c0 >> 5) * HDIM + cb + (c0 & 31);
    const int grow1 = grow0 + 1;          // c1 in same gate (c0 even)

    // ---- weights in registers: 2 cols x (16 x-k + 32 h-k) = 96 regs ----
    float wx0[16], wx1[16], wh0[32], wh1[32];
    {
        const float* s0 = W_ih + (size_t)grow0 * IN_DIM + kq * 16;
        const float* s1 = W_ih + (size_t)grow1 * IN_DIM + kq * 16;
        #pragma unroll
        for (int i = 0; i < 16; i++) { wx0[i] = __ldg(s0 + i); wx1[i] = __ldg(s1 + i); }
        const float* h0 = W_hh + (size_t)grow0 * HDIM + kq * 32;
        const float* h1 = W_hh + (size_t)grow1 * HDIM + kq * 32;
        #pragma unroll
        for (int i = 0; i < 32; i++) { wh0[i] = __ldg(h0 + i); wh1[i] = __ldg(h1 + i); }
    }

    // ---- smem preload ----
    for (int i = tid; i < 16 * HDIM; i += NTHR) {
        int o = i >> 8, k = i & 255;
        sWo[o * WOPAD + k] = W_out[(rank * 16 + o) * HDIM + k];
    }
    if (tid < 128) {
        int gr = (tid >> 5) * HDIM + cb + (tid & 31);
        sBias[tid] = b_ih[gr] + b_hh[gr];
    }
    if (tid < 16) sBOut[tid] = b_out[rank * 16 + tid];

    // zero both act buffers (h_0 = 0), x_0 transposed into buf0
    for (int i = tid; i < 2 * 384 * 4; i += NTHR) sAct[i] = 0.0f;
    __syncthreads();
    if (tid < 128) {
        int r = tid >> 5, k5 = tid & 31;
        float4 v = *(const float4*)(input + ((size_t)rbase + r) * IN_DIM + k5 * 4);
        sAct[(k5 * 4 + 0) * 4 + r] = v.x;
        sAct[(k5 * 4 + 1) * 4 + r] = v.y;
        sAct[(k5 * 4 + 2) * 4 + r] = v.z;
        sAct[(k5 * 4 + 3) * 4 + r] = v.w;
    }
    __syncthreads();

    const size_t Y_TOTAL = (size_t)T_STEPS * BATCH * OUT_DIM;
    const bool write_tail = (out_size >= (int)(Y_TOTAL + 2 * BATCH * HDIM));

    float c_reg = 0.0f;   // cell state (r=tid>>5, c=tid&31), threads 0-127

    for (int t = 0; t < T_STEPS; t++) {
        const int buf = t & 1;
        float* A  = sAct + buf * 1536;
        float* An = sAct + (1 - buf) * 1536;

        // ---- phase 1: issue h_t fill LDGs; latency hides under x-GEMM ----
        float4 hv;
        if (tid < 256 && t > 0)
            hv = __ldcg(((const float4*)g_hT[grp][buf]) + tid);

        // ---- phase 2: x-part GEMM (K=128, 8-way split, 2 cols) ----
        unsigned long long a001 = 0ULL, a023 = 0ULL, a101 = 0ULL, a123 = 0ULL;
        {
            const ulonglong2* av = ((const ulonglong2*)A) + kq * 16;
            #pragma unroll
            for (int i = 0; i < 16; i++) {
                ulonglong2 p = av[i];
                unsigned long long wp0, wp1;
                unsigned u0 = __float_as_uint(wx0[i]), u1 = __float_as_uint(wx1[i]);
                asm("mov.b64 %0, {%1, %1};" : "=l"(wp0) : "r"(u0));
                asm("mov.b64 %0, {%1, %1};" : "=l"(wp1) : "r"(u1));
                asm("fma.rn.f32x2 %0, %1, %2, %0;" : "+l"(a001) : "l"(wp0), "l"(p.x));
                asm("fma.rn.f32x2 %0, %1, %2, %0;" : "+l"(a023) : "l"(wp0), "l"(p.y));
                asm("fma.rn.f32x2 %0, %1, %2, %0;" : "+l"(a101) : "l"(wp1), "l"(p.x));
                asm("fma.rn.f32x2 %0, %1, %2, %0;" : "+l"(a123) : "l"(wp1), "l"(p.y));
            }
        }

        // ---- phase 3: land the fill ----
        if (tid < 256 && t > 0)
            ((float4*)A)[128 + tid] = hv;
        __syncthreads();

        // ---- phase 4: h-part GEMM (K=256, 8-way split, 2 cols; critical) ----
        {
            const ulonglong2* av = ((const ulonglong2*)A) + 128 + kq * 32;
            #pragma unroll
            for (int i = 0; i < 32; i++) {
                ulonglong2 p = av[i];
                unsigned long long wp0, wp1;
                unsigned u0 = __float_as_uint(wh0[i]), u1 = __float_as_uint(wh1[i]);
                asm("mov.b64 %0, {%1, %1};" : "=l"(wp0) : "r"(u0));
                asm("mov.b64 %0, {%1, %1};" : "=l"(wp1) : "r"(u1));
                asm("fma.rn.f32x2 %0, %1, %2, %0;" : "+l"(a001) : "l"(wp0), "l"(p.x));
                asm("fma.rn.f32x2 %0, %1, %2, %0;" : "+l"(a023) : "l"(wp0), "l"(p.y));
                asm("fma.rn.f32x2 %0, %1, %2, %0;" : "+l"(a101) : "l"(wp1), "l"(p.x));
                asm("fma.rn.f32x2 %0, %1, %2, %0;" : "+l"(a123) : "l"(wp1), "l"(p.y));
            }
            unsigned u0, u1, u2, u3;
            asm("mov.b64 {%0, %1}, %2;" : "=r"(u0), "=r"(u1) : "l"(a001));
            asm("mov.b64 {%0, %1}, %2;" : "=r"(u2), "=r"(u3) : "l"(a023));
            *(float4*)(sP + (kq * 128 + c0) * 4) =
                make_float4(__uint_as_float(u0), __uint_as_float(u1),
                            __uint_as_float(u2), __uint_as_float(u3));
            asm("mov.b64 {%0, %1}, %2;" : "=r"(u0), "=r"(u1) : "l"(a101));
            asm("mov.b64 {%0, %1}, %2;" : "=r"(u2), "=r"(u3) : "l"(a123));
            *(float4*)(sP + (kq * 128 + c1) * 4) =
                make_float4(__uint_as_float(u0), __uint_as_float(u1),
                            __uint_as_float(u2), __uint_as_float(u3));
        }
        __syncthreads();

        const unsigned tgt = base + 1 + (unsigned)t;

        // ---- phase 5: reduce+cell+release (w0-3) | x-prefetch+POLL (w4-7) | y (w8-15) ----
        if (tid < 128) {
            const float4* p4 = (const float4*)sP;
            float b = sBias[tid];
            float4 s = make_float4(b, b, b, b);
            #pragma unroll
            for (int q = 0; q < 8; q++) {
                float4 v = p4[q * 128 + tid];
                s.x += v.x; s.y += v.y; s.z += v.z; s.w += v.w;
            }
            *(float4*)(sG + tid * 4) = s;
            asm volatile("bar.sync 1, 128;" ::: "memory");

            const int r = tid >> 5, c = tid & 31;
            float gi = sG[(0 * 32 + c) * 4 + r];
            float gf = sG[(1 * 32 + c) * 4 + r];
            float gg = sG[(2 * 32 + c) * 4 + r];
            float go = sG[(3 * 32 + c) * 4 + r];
            float i_ = 1.0f / (1.0f + __expf(-gi));
            float f_ = 1.0f / (1.0f + __expf(-gf));
            float gv = tanhf(gg);
            float o_ = 1.0f / (1.0f + __expf(-go));
            float cn = f_ * c_reg + i_ * gv;
            float hn = o_ * tanhf(cn);
            c_reg = cn;

            __stcg(&g_hT[grp][1 - buf][(cb + c) * 4 + r], hn);

            if (t == T_STEPS - 1 && write_tail) {
                out[Y_TOTAL + (size_t)(rbase + r) * HDIM + cb + c] = hn;
                out[Y_TOTAL + BATCH * HDIM + (size_t)(rbase + r) * HDIM + cb + c] = cn;
            }
            asm volatile("bar.sync 1, 128;" ::: "memory");
            if (tid == 0) st_rel(&g_flags[bid].v, tgt);
        } else if (tid < 256) {
            // x-prefetch (all 128), then 8 threads poll concurrently with cell
            if (t + 1 < T_STEPS) {
                int xr = (tid - 128) >> 5, xk5 = (tid - 128) & 31;
                float4 v = __ldcg((const float4*)(input
                        + ((size_t)(t + 1) * BATCH + rbase + xr) * IN_DIM + xk5 * 4));
                An[(xk5 * 4 + 0) * 4 + xr] = v.x;
                An[(xk5 * 4 + 1) * 4 + xr] = v.y;
                An[(xk5 * 4 + 2) * 4 + xr] = v.z;
                An[(xk5 * 4 + 3) * 4 + xr] = v.w;
            }
            if (tid < 136) {
                const unsigned* p = &g_flags[grp * 8 + (tid - 128)].v;
                while (ld_acq(p) < tgt) { }
            }
        } else if (t > 0) {
            const int slot = tid - 256;
            const int o = slot >> 4, ks = slot & 15;
            float y0 = 0.f, y1 = 0.f, y2 = 0.f, y3 = 0.f;
            const float* wo = sWo + o * WOPAD + ks;
            const float4* ah = ((const float4*)A) + 128 + ks;
            #pragma unroll
            for (int i = 0; i < 16; i++) {
                float w = wo[i * 16];
                float4 h4 = ah[i * 16];
                y0 += w * h4.x; y1 += w * h4.y; y2 += w * h4.z; y3 += w * h4.w;
            }
            #pragma unroll
            for (int s = 1; s <= 8; s <<= 1) {
                y0 += __shfl_xor_sync(0xffffffffu, y0, s);
                y1 += __shfl_xor_sync(0xffffffffu, y1, s);
                y2 += __shfl_xor_sync(0xffffffffu, y2, s);
                y3 += __shfl_xor_sync(0xffffffffu, y3, s);
            }
            if (ks == 0) {
                float b = sBOut[o];
                size_t yb = ((size_t)(t - 1) * BATCH + rbase) * OUT_DIM
                            + (size_t)rank * 16 + o;
                out[yb + 0 * OUT_DIM] = y0 + b;
                out[yb + 1 * OUT_DIM] = y1 + b;
                out[yb + 2 * OUT_DIM] = y2 + b;
                out[yb + 3 * OUT_DIM] = y3 + b;
            }
        }
        __syncthreads();   // joins cell release, pollers, prefetch, y-GEMM
    }

    // ---- tail: y_{T-1} from h_T (g_hT[grp][0]; final poll already passed) ----
    {
        float* A = sAct;   // buf 0
        if (tid < 256) {
            float4 v = __ldcg(((const float4*)g_hT[grp][0]) + tid);
            ((float4*)A)[128 + tid] = v;
        }
        __syncthreads();
        if (tid >= 256) {
            const int slot = tid - 256;
            const int o = slot >> 4, ks = slot & 15;
            float y0 = 0.f, y1 = 0.f, y2 = 0.f, y3 = 0.f;
            const float* wo = sWo + o * WOPAD + ks;
            const float4* ah = ((const float4*)A) + 128 + ks;
            #pragma unroll
            for (int i = 0; i < 16; i++) {
                float w = wo[i * 16];
                float4 h4 = ah[i * 16];
                y0 += w * h4.x; y1 += w * h4.y; y2 += w * h4.z; y3 += w * h4.w;
            }
            #pragma unroll
            for (int s = 1; s <= 8; s <<= 1) {
                y0 += __shfl_xor_sync(0xffffffffu, y0, s);
                y1 += __shfl_xor_sync(0xffffffffu, y1, s);
                y2 += __shfl_xor_sync(0xffffffffu, y2, s);
                y3 += __shfl_xor_sync(0xffffffffu, y3, s);
            }
            if (ks == 0) {
                float b = sBOut[o];
                size_t yb = ((size_t)(T_STEPS - 1) * BATCH + rbase) * OUT_DIM
                            + (size_t)rank * 16 + o;
                out[yb + 0 * OUT_DIM] = y0 + b;
                out[yb + 1 * OUT_DIM] = y1 + b;
                out[yb + 2 * OUT_DIM] = y2 + b;
                out[yb + 3 * OUT_DIM] = y3 + b;
            }
        }
    }
}

extern "C" void kernel_launch(void* const* d_in, const int* in_sizes, int n_in,
                              void* d_out, int out_size) {
    const float* input = (const float*)d_in[0];
    const float* W_ih  = (const float*)d_in[1];
    const float* W_hh  = (const float*)d_in[2];
    const float* b_ih  = (const float*)d_in[3];
    const float* b_hh  = (const float*)d_in[4];
    const float* W_out = (const float*)d_in[5];
    const float* b_out = (const float*)d_in[6];
    float* out = (float*)d_out;
    (void)in_sizes; (void)n_in;

    cudaFuncSetAttribute(lstm_col2_kernel,
                         cudaFuncAttributeMaxDynamicSharedMemorySize, SMEM_BYTES);
    lstm_col2_kernel<<<NBLK, NTHR, SMEM_BYTES>>>(
        input, W_ih, W_hh, b_ih, b_hh, W_out, b_out, out, out_size);
}